// round 11
// baseline (speedup 1.0000x reference)
#include <cuda_runtime.h>

#define NGRID 48
#define N3 (NGRID * NGRID * NGRID)
#define NATOMS_MAX 1024
#define TILE 4
#define TILES_X (NGRID / TILE)        // 12
#define NBLOCKS (TILES_X * TILES_X)   // 144
#define NTHREADS 1024

// r^2 exactly as the reference: float32((1.5*1.52)**2), product in double.
__device__ __forceinline__ float ref_r2() {
    const double r = 1.5 * 1.52;
    return (float)(r * r);
}

// Exact reference-rounded test with precomputed voxel coord zf = 0.5*z
// (half-integers are exact in fp32): RN(sxy + RN(dz*dz)) < R2.
__device__ __forceinline__ bool exact_pass_f(float sxy, float az, float zf, float R2) {
    const float dz = __fsub_rn(az, zf);
    return __fadd_rn(sxy, __fmul_rn(dz, dz)) < R2;
}

// Per-atom interval resolution: sqrt.rn boundary estimate (+/-1 index) plus
// two exact reference-rounded tests per end, branchless. Returns run bits.
__device__ __forceinline__ unsigned long long atom_run(float4 a, float px,
                                                       float py, float R2) {
    const float dx  = __fsub_rn(a.x, px);
    const float dy  = __fsub_rn(a.y, py);
    const float sxy = __fadd_rn(__fmul_rn(dx, dx), __fmul_rn(dy, dy));
    if (sxy >= R2) return 0ull;           // rigorous: RN(sxy+dz^2) >= sxy

    const float azj = a.z;
    const float rad = sqrtf(__fsub_rn(R2, sxy));
    const float az2 = __fadd_rn(azj, azj);            // 2*az (exact)
    const float r2x = __fadd_rn(rad, rad);            // 2*rad
    const int e = __float2int_ru(__fsub_rn(az2, r2x)); // ceil(2(az-rad))
    const int f = __float2int_rd(__fadd_rn(az2, r2x)); // floor(2(az+rad))

    const float ze = 0.5f * (float)e;                 // exact half-integers
    const float zf = 0.5f * (float)f;

    // Low end: true zl in {e-1, e, e+1}; high end mirrored.
    const bool pl0 = exact_pass_f(sxy, azj, ze - 0.5f, R2);
    const bool pl1 = exact_pass_f(sxy, azj, ze,        R2);
    const bool ph0 = exact_pass_f(sxy, azj, zf + 0.5f, R2);
    const bool ph1 = exact_pass_f(sxy, azj, zf,        R2);
    int zl = pl0 ? e - 1 : (pl1 ? e : e + 1);
    int zh = ph0 ? f + 1 : (ph1 ? f : f - 1);
    zl = max(zl, 0);
    zh = min(zh, NGRID - 1);
    const int len = zh - zl + 1;                      // <= 48
    return (len > 0) ? (((1ull << len) - 1ull) << zl) : 0ull;
}

__global__ __launch_bounds__(NTHREADS)
void wat_mask_kernel(const float* __restrict__ vecs, int n_atoms,
                     float* __restrict__ out) {
    __shared__ float4 satom[NATOMS_MAX];  // compacted culled atoms
    __shared__ int scnt[32];              // per-warp match counts

    const float R2 = ref_r2();            // ~5.1984
    const float RM = 2.2802f;             // > sqrt(R2): conservative margin

    const int bx = blockIdx.x % TILES_X;
    const int by = blockIdx.x / TILES_X;
    const int x0 = bx * TILE;
    const int y0 = by * TILE;

    const int tid  = threadIdx.x;
    const int wid  = tid >> 5;            // 32 warps
    const int lane = tid & 31;

    // ---- Phase 1: one atom per thread, cull vs expanded tile AABB.
    const bool v0 = (tid < n_atoms);
    float ax = 0.f, ay = 0.f, az = 0.f;
    if (v0) { ax = vecs[3*tid]; ay = vecs[3*tid+1]; az = vecs[3*tid+2]; }

    const float xmin = 0.5f * (float)x0 - RM;
    const float xmax = 0.5f * (float)(x0 + TILE - 1) + RM;
    const float ymin = 0.5f * (float)y0 - RM;
    const float ymax = 0.5f * (float)(y0 + TILE - 1) + RM;

    const bool match = v0 && ax >= xmin && ax <= xmax
                          && ay >= ymin && ay <= ymax;
    const unsigned m = __ballot_sync(0xffffffffu, match);
    if (lane == 0) scnt[wid] = __popc(m);
    __syncthreads();

    // ---- Offsets via REDUX: base_w = sum of counts of warps < wid.
    const int c_l   = scnt[lane];
    const int base  = __reduce_add_sync(0xffffffffu, (lane < wid) ? c_l : 0);
    const int total = __reduce_add_sync(0xffffffffu, c_l);

    if (match) {
        const int p = base + __popc(m & ((1u << lane) - 1u));
        satom[p] = make_float4(ax, ay, az, 0.f);
    }
    __syncthreads();

    // Warps 16-31 are done (they participated in both barriers).
    if (wid >= TILE * TILE) return;

    // ---- Phase 2: one warp per column, software-pipelined over the culled
    // atom list: next trip's LDS.128 is issued before the current trip's
    // FP chain so shared-memory latency overlaps computation.
    const int cx = wid >> 2;
    const int cy = wid & 3;
    const float px = 0.5f * (float)(x0 + cx);         // exact in fp32
    const float py = 0.5f * (float)(y0 + cy);

    unsigned long long mask = 0ull;
    int j = lane;
    if (j < total) {
        float4 a_cur = satom[j];
        while (true) {
            const int jn = j + 32;
            float4 a_nxt;
            const bool more = (jn < total);
            if (more) a_nxt = satom[jn];              // prefetch next trip
            mask |= atom_run(a_cur, px, py, R2);
            if (!more) break;
            a_cur = a_nxt;
            j = jn;
        }
    }
    const unsigned lo = __reduce_or_sync(0xffffffffu, (unsigned)mask);
    const unsigned hi = __reduce_or_sync(0xffffffffu, (unsigned)(mask >> 32));
    mask = (unsigned long long)lo | ((unsigned long long)hi << 32);

    // ---- Epilogue: warp-direct stores, no barrier. Lanes 0-11 write ch0,
    // lanes 12-23 write ch1 (12 float4 each = 192B contiguous per channel).
    if (lane < 24) {
        const int ch = (lane >= 12);
        const int zq = ch ? lane - 12 : lane;
        const unsigned bits = (unsigned)(mask >> (4 * zq)) & 0xFu;

        const float on  = ch ? 25.0f : 1.0f;
        const float off = ch ? 1.0f  : 0.0f;
        float4 v;
        v.x = (bits & 1u) ? on : off;
        v.y = (bits & 2u) ? on : off;
        v.z = (bits & 4u) ? on : off;
        v.w = (bits & 8u) ? on : off;

        const int gx = x0 + cx;
        const int gy = y0 + cy;
        const int idx = ch * N3 + (gx * NGRID + gy) * NGRID + 4 * zq;
        *reinterpret_cast<float4*>(out + idx) = v;
    }
}

extern "C" void kernel_launch(void* const* d_in, const int* in_sizes, int n_in,
                              void* d_out, int out_size) {
    const float* vecs = (const float*)d_in[0];
    const int n_atoms = in_sizes[0] / 3;
    float* out = (float*)d_out;
    wat_mask_kernel<<<NBLOCKS, NTHREADS>>>(vecs, n_atoms, out);
}